// round 14
// baseline (speedup 1.0000x reference)
#include <cuda_runtime.h>
#include <stdint.h>

// ============================================================================
// ControlPointBetaNoise — exact re-implementation of the JAX reference.
// R13 = R12 (record holder, 1193.7us) resubmitted unchanged: two-phase
// compaction + full state staging. All structural levers tested across
// R1-R12; remaining run-to-run spread is DVFS/scheduler variance.
//   Phase 1: block-per-row bicubic, 1 px/thread, straight-line first
//            attempts; failures enqueue full sampler state (48B).
//   Phase 2: resumes rejection loops directly from staged state.
// ============================================================================

static const unsigned B_ = 32, C_ = 3, H_ = 512, W_ = 512;
static const unsigned PIX_PER_IMG = H_ * W_;              // 262144 = 1<<18

struct U2 { uint32_t a, b; };

__host__ __device__ __forceinline__ uint32_t rotl32(uint32_t x, int r) {
#ifdef __CUDA_ARCH__
  return __funnelshift_l(x, x, r);
#else
  return (x << r) | (x >> (32 - r));
#endif
}

// threefry2x32, 20 rounds — matches jax._src.prng.threefry2x32 exactly.
__host__ __device__ __forceinline__ U2 tf2x32(uint32_t k0, uint32_t k1,
                                              uint32_t x0, uint32_t x1) {
  uint32_t ks2 = k0 ^ k1 ^ 0x1BD11BDAu;
  x0 += k0; x1 += k1;
#define TF_RND(r) { x0 += x1; x1 = rotl32(x1, (r)); x1 ^= x0; }
  TF_RND(13) TF_RND(15) TF_RND(26) TF_RND(6)
  x0 += k1;  x1 += ks2 + 1u;
  TF_RND(17) TF_RND(29) TF_RND(16) TF_RND(24)
  x0 += ks2; x1 += k0 + 2u;
  TF_RND(13) TF_RND(15) TF_RND(26) TF_RND(6)
  x0 += k0;  x1 += k1 + 3u;
  TF_RND(17) TF_RND(29) TF_RND(16) TF_RND(24)
  x0 += k1;  x1 += ks2 + 4u;
  TF_RND(13) TF_RND(15) TF_RND(26) TF_RND(6)
  x0 += ks2; x1 += k0 + 5u;
#undef TF_RND
  return U2{x0, x1};
}

__device__ __forceinline__ uint32_t bits_scalar(uint32_t k0, uint32_t k1) {
  U2 r = tf2x32(k0, k1, 0u, 0u);
  return r.a ^ r.b;
}

// uniform [0,1): bitcast((bits>>9)|0x3f800000) - 1.0  (matches jax._uniform)
__device__ __forceinline__ float u01_from_bits(uint32_t bits) {
  return __uint_as_float((bits >> 9) | 0x3F800000u) - 1.0f;
}

// XLA f32 erf_inv (Giles polynomial) — what lax.erf_inv lowers to.
__device__ __forceinline__ float erfinv_f32(float x) {
  float w = -log1pf(-x * x);
  float p;
  if (w < 5.0f) {
    w -= 2.5f;
    p = 2.81022636e-08f;
    p = fmaf(p, w, 3.43273939e-07f);
    p = fmaf(p, w, -3.5233877e-06f);
    p = fmaf(p, w, -4.39150654e-06f);
    p = fmaf(p, w, 0.00021858087f);
    p = fmaf(p, w, -0.00125372503f);
    p = fmaf(p, w, -0.00417768164f);
    p = fmaf(p, w, 0.246640727f);
    p = fmaf(p, w, 1.50140941f);
  } else {
    w = sqrtf(w) - 3.0f;
    p = -0.000200214257f;
    p = fmaf(p, w, 0.000100950558f);
    p = fmaf(p, w, 0.00134934322f);
    p = fmaf(p, w, -0.00367342844f);
    p = fmaf(p, w, 0.00573950773f);
    p = fmaf(p, w, -0.0076224613f);
    p = fmaf(p, w, 0.00943887047f);
    p = fmaf(p, w, 1.00167406f);
    p = fmaf(p, w, 2.83297682f);
  }
  return p * x;
}

__device__ __forceinline__ float normal_from_key(uint32_t k0, uint32_t k1) {
  uint32_t bits = bits_scalar(k0, k1);
  float f = u01_from_bits(bits);
  const float LO = __uint_as_float(0xBF7FFFFFu);  // nextafter(-1,0)
  float u = fmaxf(LO, f * 2.0f + LO);
  return 1.41421356237f * erfinv_f32(u);
}

// ---------------------------------------------------------------------------
// Bicubic weight table (jax.image.resize "bicubic", Keys a=-0.5, renormalized)
// + queue reset folded in.
// ---------------------------------------------------------------------------
__device__ float g_w[512][8];

struct __align__(16) QE {
  uint32_t kc0, kc1, xk0, xk1;   // failed gamma: outer + inner keys
  float x, v, U, d;              // failed gamma: current attempt + d
  float c, zc, d2, c2;           // c; zc=log(db/da); d2,c2 for double-fail (B)
};

static const unsigned QCAP = 1u << 23;
__device__ uint32_t g_qhdr[QCAP];
__device__ QE g_qstate[QCAP];
__device__ uint32_t g_count;

__global__ void weights_kernel() {
  int j = threadIdx.x;  // 0..511
  if (j == 0) g_count = 0u;
  float s = (j + 0.5f) * (1.0f / 64.0f) - 0.5f;
  float w[8]; float sum = 0.0f;
#pragma unroll
  for (int i = 0; i < 8; i++) {
    float x = fabsf(s - (float)i);
    float out = ((1.5f * x - 2.5f) * x) * x + 1.0f;
    if (x >= 1.0f) out = ((-0.5f * x + 2.5f) * x - 4.0f) * x + 2.0f;
    if (x >= 2.0f) out = 0.0f;
    w[i] = out; sum += out;
  }
#pragma unroll
  for (int i = 0; i < 8; i++) g_w[j][i] = w[i] / sum;
}

// ---------------------------------------------------------------------------
// Marsaglia–Tsang continuation loop (resumes from a computed attempt).
// ---------------------------------------------------------------------------
__device__ __forceinline__ float mt_finish(uint32_t kl0, uint32_t kl1,
                                           uint32_t xk0, uint32_t xk1,
                                           float x, float v, float U,
                                           float d, float c) {
  for (;;) {
    while (v <= 0.0f) {
      U2 nxt = tf2x32(xk0, xk1, 0u, 0u);
      xk0 = nxt.a; xk1 = nxt.b;
      U2 sub = tf2x32(xk0, xk1, 0u, 1u);
      x = normal_from_key(sub.a, sub.b);
      v = fmaf(c, x, 1.0f);
    }
    float X = x * x;
    float V = (v * v) * v;
    float lV = logf(V);
    bool rej = (U >= 1.0f - 0.0331f * (X * X)) &&
               (logf(U) >= 0.5f * X + d * (1.0f - V + lV));
    if (!rej) return lV;
    U2 nk = tf2x32(kl0, kl1, 0u, 0u);
    kl0 = nk.a; kl1 = nk.b;
    U2 xk = tf2x32(kl0, kl1, 0u, 1u);
    xk0 = xk.a; xk1 = xk.b;
    U2 Uk = tf2x32(kl0, kl1, 0u, 2u);
    U2 sub = tf2x32(xk0, xk1, 0u, 1u);
    x = normal_from_key(sub.a, sub.b);
    v = fmaf(c, x, 1.0f);
    U = u01_from_bits(bits_scalar(Uk.a, Uk.b));
  }
}

struct FA { U2 kc, xk; float x, v, U; };

__device__ __forceinline__ FA first_attempt(uint32_t K0, uint32_t K1,
                                            uint32_t e, float c) {
  FA f;
  U2 ek = tf2x32(K0, K1, 0u, e);
  f.kc = tf2x32(ek.a, ek.b, 0u, 0u);
  f.xk = tf2x32(f.kc.a, f.kc.b, 0u, 1u);
  U2 Uk = tf2x32(f.kc.a, f.kc.b, 0u, 2u);
  U2 sb = tf2x32(f.xk.a, f.xk.b, 0u, 1u);
  f.x = normal_from_key(sb.a, sb.b);
  f.v = fmaf(c, f.x, 1.0f);
  f.U = u01_from_bits(bits_scalar(Uk.a, Uk.b));
  return f;
}

__device__ __forceinline__ bool try_accept(const FA& f, float d, float& lV) {
  float X = f.x * f.x;
  float V = (f.v * f.v) * f.v;
  float l = logf(V);
  bool rej = (f.U >= 1.0f - 0.0331f * (X * X)) &&
             (logf(f.U) >= 0.5f * X + d * (1.0f - V + l));
  lV = l;
  return (f.v > 0.0f) && !rej;
}

// ---------------------------------------------------------------------------
// Phase 1: one block per (image, row); one pixel per thread (512 threads).
// ---------------------------------------------------------------------------
__global__ void __launch_bounds__(512)
phase1_kernel(const float* __restrict__ mcp, float* __restrict__ out,
              uint32_t ka0, uint32_t ka1, uint32_t kb0, uint32_t kb1) {
  __shared__ float Gs[64];
  __shared__ float trow[8];
  unsigned bc = blockIdx.y;
  unsigned y  = blockIdx.x;
  unsigned tid = threadIdx.x;   // = x coordinate

  if (tid < 64) Gs[tid] = fmaf(__ldg(mcp + bc * 64u + tid), 0.9f, 0.05f);
  __syncthreads();
  if (tid < 8) {
    const float* wy = g_w[y];
    float tj = 0.0f;
#pragma unroll
    for (int i = 0; i < 8; i++) tj = fmaf(wy[i], Gs[i * 8 + tid], tj);
    trow[tid] = tj;
  }
  __syncthreads();

  float m = 0.0f;
  {
    const float* wx = g_w[tid];
#pragma unroll
    for (int j = 0; j < 8; j++) m = fmaf(wx[j], trow[j], m);
  }

  m = fminf(fmaxf(m, 0.05f), 0.95f);
  float t  = m * (1.0f - m);
  float sd = t - 1e-6f;
  float V_ = t / (sd * sd) - 1.0f;
  float Alpha = fmaxf(m * V_, 0.0f) + 1e-6f;          // >= 1.0027
  float Beta  = fmaxf((1.0f - m) * V_, 0.0f) + 1e-6f; // >= 1.0027
  float da = Alpha - (1.0f / 3.0f);
  float ca = (1.0f / 3.0f) * rsqrtf(da);
  float db = Beta - (1.0f / 3.0f);
  float cb = (1.0f / 3.0f) * rsqrtf(db);

  unsigned e = bc * PIX_PER_IMG + y * 512u + tid;

  FA fa = first_attempt(ka0, ka1, e, ca);
  FA fb = first_attempt(kb0, kb1, e, cb);

  float lVa, lVb;
  bool okA = try_accept(fa, da, lVa);
  bool okB = try_accept(fb, db, lVb);
  bool ok = okA && okB;

  float zc = logf(__fdividef(db, da));

  if (ok) {
    float z = zc + (lVb - lVa);
    out[e] = __fdividef(1.0f, 1.0f + __expf(z));
  } else if (okA != okB) {
    out[e] = okA ? lVa : lVb;   // stage accepted gamma's logV
  }

  // warp-aggregated enqueue of failed-state entries
  unsigned mask = __ballot_sync(0xFFFFFFFFu, !ok);
  if (!ok) {
    unsigned leader = __ffs(mask) - 1u;
    unsigned lane = tid & 31u;
    uint32_t base = 0;
    if (lane == leader) base = atomicAdd(&g_count, (uint32_t)__popc(mask));
    base = __shfl_sync(mask, base, leader);
    uint32_t slot = base + __popc(mask & ((1u << lane) - 1u));
    if (slot < QCAP) {
      uint32_t flags = (okA ? 0u : (1u << 30)) | (okB ? 0u : (1u << 31));
      g_qhdr[slot] = e | flags;
      const FA& ff = okA ? fb : fa;   // failed gamma (A preferred if both)
      QE q;
      q.kc0 = ff.kc.a; q.kc1 = ff.kc.b;
      q.xk0 = ff.xk.a; q.xk1 = ff.xk.b;
      q.x = ff.x; q.v = ff.v; q.U = ff.U;
      q.d = okA ? db : da;
      q.c = okA ? cb : ca;
      q.zc = zc;
      q.d2 = db; q.c2 = cb;          // used only for double-fail (B replay)
      g_qstate[slot] = q;
    }
  }
}

// ---------------------------------------------------------------------------
// Phase 2: resume rejection loops directly from staged state.
// ---------------------------------------------------------------------------
__global__ void __launch_bounds__(256)
phase2_kernel(float* __restrict__ out,
              uint32_t kb0, uint32_t kb1) {
  uint32_t count = min(g_count, QCAP);
  unsigned stride = gridDim.x * 256u;
  for (uint32_t i = blockIdx.x * 256u + threadIdx.x; i < count; i += stride) {
    uint32_t hdr = g_qhdr[i];
    unsigned e = hdr & 0x01FFFFFFu;
    bool fA = (hdr >> 30) & 1u;
    bool fB = (hdr >> 31) & 1u;
    QE q = g_qstate[i];

    float lv = mt_finish(q.kc0, q.kc1, q.xk0, q.xk1,
                         q.x, q.v, q.U, q.d, q.c);

    float z;
    if (fA && fB) {
      FA fb = first_attempt(kb0, kb1, e, q.c2);
      float lvb = mt_finish(fb.kc.a, fb.kc.b, fb.xk.a, fb.xk.b,
                            fb.x, fb.v, fb.U, q.d2, q.c2);
      z = q.zc + (lvb - lv);
    } else {
      float staged = out[e];
      z = fA ? (q.zc + staged - lv) : (q.zc + lv - staged);
    }
    out[e] = __fdividef(1.0f, 1.0f + __expf(z));
  }
}

// ---------------------------------------------------------------------------
extern "C" void kernel_launch(void* const* d_in, const int* in_sizes, int n_in,
                              void* d_out, int out_size) {
  const float* mcp = (const float*)d_in[1];
  for (int i = 0; i < n_in; i++)
    if (in_sizes[i] == 6144) { mcp = (const float*)d_in[i]; break; }

  // root key = threefry_seed(1234) = (0, 1234); key_a, key_b = split(root)
  U2 ka = tf2x32(0u, 1234u, 0u, 0u);
  U2 kb = tf2x32(0u, 1234u, 0u, 1u);

  weights_kernel<<<1, 512>>>();
  dim3 grid(H_, B_ * C_);   // (row, image)
  phase1_kernel<<<grid, 512>>>(mcp, (float*)d_out, ka.a, ka.b, kb.a, kb.b);
  phase2_kernel<<<4096, 256>>>((float*)d_out, kb.a, kb.b);
}

// round 15
// speedup vs baseline: 1.0031x; 1.0031x over previous
#include <cuda_runtime.h>
#include <stdint.h>

// ============================================================================
// ControlPointBetaNoise — exact re-implementation of the JAX reference.
// R14 = R13 arithmetic (bit-identical) + phase-1 occupancy fix:
//   256-thread blocks with __launch_bounds__(256, 6) — forces <=42 regs and
//   6 resident blocks -> 48 warps/SM (75% occ vs the measured 51% at 512
//   threads). Phase 1 is latency-bound (established R11), so more warps =
//   more latency hiding. Each block covers half a row; trow recomputed per
//   half-row (negligible).
// ============================================================================

static const unsigned B_ = 32, C_ = 3, H_ = 512, W_ = 512;
static const unsigned PIX_PER_IMG = H_ * W_;              // 262144 = 1<<18

struct U2 { uint32_t a, b; };

__host__ __device__ __forceinline__ uint32_t rotl32(uint32_t x, int r) {
#ifdef __CUDA_ARCH__
  return __funnelshift_l(x, x, r);
#else
  return (x << r) | (x >> (32 - r));
#endif
}

// threefry2x32, 20 rounds — matches jax._src.prng.threefry2x32 exactly.
__host__ __device__ __forceinline__ U2 tf2x32(uint32_t k0, uint32_t k1,
                                              uint32_t x0, uint32_t x1) {
  uint32_t ks2 = k0 ^ k1 ^ 0x1BD11BDAu;
  x0 += k0; x1 += k1;
#define TF_RND(r) { x0 += x1; x1 = rotl32(x1, (r)); x1 ^= x0; }
  TF_RND(13) TF_RND(15) TF_RND(26) TF_RND(6)
  x0 += k1;  x1 += ks2 + 1u;
  TF_RND(17) TF_RND(29) TF_RND(16) TF_RND(24)
  x0 += ks2; x1 += k0 + 2u;
  TF_RND(13) TF_RND(15) TF_RND(26) TF_RND(6)
  x0 += k0;  x1 += k1 + 3u;
  TF_RND(17) TF_RND(29) TF_RND(16) TF_RND(24)
  x0 += k1;  x1 += ks2 + 4u;
  TF_RND(13) TF_RND(15) TF_RND(26) TF_RND(6)
  x0 += ks2; x1 += k0 + 5u;
#undef TF_RND
  return U2{x0, x1};
}

__device__ __forceinline__ uint32_t bits_scalar(uint32_t k0, uint32_t k1) {
  U2 r = tf2x32(k0, k1, 0u, 0u);
  return r.a ^ r.b;
}

// uniform [0,1): bitcast((bits>>9)|0x3f800000) - 1.0  (matches jax._uniform)
__device__ __forceinline__ float u01_from_bits(uint32_t bits) {
  return __uint_as_float((bits >> 9) | 0x3F800000u) - 1.0f;
}

// XLA f32 erf_inv (Giles polynomial) — what lax.erf_inv lowers to.
__device__ __forceinline__ float erfinv_f32(float x) {
  float w = -log1pf(-x * x);
  float p;
  if (w < 5.0f) {
    w -= 2.5f;
    p = 2.81022636e-08f;
    p = fmaf(p, w, 3.43273939e-07f);
    p = fmaf(p, w, -3.5233877e-06f);
    p = fmaf(p, w, -4.39150654e-06f);
    p = fmaf(p, w, 0.00021858087f);
    p = fmaf(p, w, -0.00125372503f);
    p = fmaf(p, w, -0.00417768164f);
    p = fmaf(p, w, 0.246640727f);
    p = fmaf(p, w, 1.50140941f);
  } else {
    w = sqrtf(w) - 3.0f;
    p = -0.000200214257f;
    p = fmaf(p, w, 0.000100950558f);
    p = fmaf(p, w, 0.00134934322f);
    p = fmaf(p, w, -0.00367342844f);
    p = fmaf(p, w, 0.00573950773f);
    p = fmaf(p, w, -0.0076224613f);
    p = fmaf(p, w, 0.00943887047f);
    p = fmaf(p, w, 1.00167406f);
    p = fmaf(p, w, 2.83297682f);
  }
  return p * x;
}

__device__ __forceinline__ float normal_from_key(uint32_t k0, uint32_t k1) {
  uint32_t bits = bits_scalar(k0, k1);
  float f = u01_from_bits(bits);
  const float LO = __uint_as_float(0xBF7FFFFFu);  // nextafter(-1,0)
  float u = fmaxf(LO, f * 2.0f + LO);
  return 1.41421356237f * erfinv_f32(u);
}

// ---------------------------------------------------------------------------
// Bicubic weight table (jax.image.resize "bicubic", Keys a=-0.5, renormalized)
// + queue reset folded in.
// ---------------------------------------------------------------------------
__device__ float g_w[512][8];

struct __align__(16) QE {
  uint32_t kc0, kc1, xk0, xk1;   // failed gamma: outer + inner keys
  float x, v, U, d;              // failed gamma: current attempt + d
  float c, zc, d2, c2;           // c; zc=log(db/da); d2,c2 for double-fail (B)
};

static const unsigned QCAP = 1u << 23;
__device__ uint32_t g_qhdr[QCAP];
__device__ QE g_qstate[QCAP];
__device__ uint32_t g_count;

__global__ void weights_kernel() {
  int j = threadIdx.x;  // 0..511
  if (j == 0) g_count = 0u;
  float s = (j + 0.5f) * (1.0f / 64.0f) - 0.5f;
  float w[8]; float sum = 0.0f;
#pragma unroll
  for (int i = 0; i < 8; i++) {
    float x = fabsf(s - (float)i);
    float out = ((1.5f * x - 2.5f) * x) * x + 1.0f;
    if (x >= 1.0f) out = ((-0.5f * x + 2.5f) * x - 4.0f) * x + 2.0f;
    if (x >= 2.0f) out = 0.0f;
    w[i] = out; sum += out;
  }
#pragma unroll
  for (int i = 0; i < 8; i++) g_w[j][i] = w[i] / sum;
}

// ---------------------------------------------------------------------------
// Marsaglia–Tsang continuation loop (resumes from a computed attempt).
// ---------------------------------------------------------------------------
__device__ __forceinline__ float mt_finish(uint32_t kl0, uint32_t kl1,
                                           uint32_t xk0, uint32_t xk1,
                                           float x, float v, float U,
                                           float d, float c) {
  for (;;) {
    while (v <= 0.0f) {
      U2 nxt = tf2x32(xk0, xk1, 0u, 0u);
      xk0 = nxt.a; xk1 = nxt.b;
      U2 sub = tf2x32(xk0, xk1, 0u, 1u);
      x = normal_from_key(sub.a, sub.b);
      v = fmaf(c, x, 1.0f);
    }
    float X = x * x;
    float V = (v * v) * v;
    float lV = logf(V);
    bool rej = (U >= 1.0f - 0.0331f * (X * X)) &&
               (logf(U) >= 0.5f * X + d * (1.0f - V + lV));
    if (!rej) return lV;
    U2 nk = tf2x32(kl0, kl1, 0u, 0u);
    kl0 = nk.a; kl1 = nk.b;
    U2 xk = tf2x32(kl0, kl1, 0u, 1u);
    xk0 = xk.a; xk1 = xk.b;
    U2 Uk = tf2x32(kl0, kl1, 0u, 2u);
    U2 sub = tf2x32(xk0, xk1, 0u, 1u);
    x = normal_from_key(sub.a, sub.b);
    v = fmaf(c, x, 1.0f);
    U = u01_from_bits(bits_scalar(Uk.a, Uk.b));
  }
}

struct FA { U2 kc, xk; float x, v, U; };

__device__ __forceinline__ FA first_attempt(uint32_t K0, uint32_t K1,
                                            uint32_t e, float c) {
  FA f;
  U2 ek = tf2x32(K0, K1, 0u, e);
  f.kc = tf2x32(ek.a, ek.b, 0u, 0u);
  f.xk = tf2x32(f.kc.a, f.kc.b, 0u, 1u);
  U2 Uk = tf2x32(f.kc.a, f.kc.b, 0u, 2u);
  U2 sb = tf2x32(f.xk.a, f.xk.b, 0u, 1u);
  f.x = normal_from_key(sb.a, sb.b);
  f.v = fmaf(c, f.x, 1.0f);
  f.U = u01_from_bits(bits_scalar(Uk.a, Uk.b));
  return f;
}

__device__ __forceinline__ bool try_accept(const FA& f, float d, float& lV) {
  float X = f.x * f.x;
  float V = (f.v * f.v) * f.v;
  float l = logf(V);
  bool rej = (f.U >= 1.0f - 0.0331f * (X * X)) &&
             (logf(f.U) >= 0.5f * X + d * (1.0f - V + l));
  lV = l;
  return (f.v > 0.0f) && !rej;
}

// ---------------------------------------------------------------------------
// Phase 1: one block per (image, half-row); one pixel per thread.
// 256 threads, 6 blocks/SM forced -> 75% occupancy for latency hiding.
// ---------------------------------------------------------------------------
__global__ void __launch_bounds__(256, 6)
phase1_kernel(const float* __restrict__ mcp, float* __restrict__ out,
              uint32_t ka0, uint32_t ka1, uint32_t kb0, uint32_t kb1) {
  __shared__ float Gs[64];
  __shared__ float trow[8];
  unsigned bc = blockIdx.y;
  unsigned y  = blockIdx.x >> 1;
  unsigned xbase = (blockIdx.x & 1u) * 256u;
  unsigned tid = threadIdx.x;
  unsigned x = xbase + tid;

  if (tid < 64) Gs[tid] = fmaf(__ldg(mcp + bc * 64u + tid), 0.9f, 0.05f);
  __syncthreads();
  if (tid < 8) {
    const float* wy = g_w[y];
    float tj = 0.0f;
#pragma unroll
    for (int i = 0; i < 8; i++) tj = fmaf(wy[i], Gs[i * 8 + tid], tj);
    trow[tid] = tj;
  }
  __syncthreads();

  float m = 0.0f;
  {
    const float* wx = g_w[x];
#pragma unroll
    for (int j = 0; j < 8; j++) m = fmaf(wx[j], trow[j], m);
  }

  m = fminf(fmaxf(m, 0.05f), 0.95f);
  float t  = m * (1.0f - m);
  float sd = t - 1e-6f;
  float V_ = t / (sd * sd) - 1.0f;
  float Alpha = fmaxf(m * V_, 0.0f) + 1e-6f;          // >= 1.0027
  float Beta  = fmaxf((1.0f - m) * V_, 0.0f) + 1e-6f; // >= 1.0027
  float da = Alpha - (1.0f / 3.0f);
  float ca = (1.0f / 3.0f) * rsqrtf(da);
  float db = Beta - (1.0f / 3.0f);
  float cb = (1.0f / 3.0f) * rsqrtf(db);

  unsigned e = bc * PIX_PER_IMG + y * 512u + x;

  FA fa = first_attempt(ka0, ka1, e, ca);
  FA fb = first_attempt(kb0, kb1, e, cb);

  float lVa, lVb;
  bool okA = try_accept(fa, da, lVa);
  bool okB = try_accept(fb, db, lVb);
  bool ok = okA && okB;

  float zc = logf(__fdividef(db, da));

  if (ok) {
    float z = zc + (lVb - lVa);
    out[e] = __fdividef(1.0f, 1.0f + __expf(z));
  } else if (okA != okB) {
    out[e] = okA ? lVa : lVb;   // stage accepted gamma's logV
  }

  // warp-aggregated enqueue of failed-state entries
  unsigned mask = __ballot_sync(0xFFFFFFFFu, !ok);
  if (!ok) {
    unsigned leader = __ffs(mask) - 1u;
    unsigned lane = tid & 31u;
    uint32_t base = 0;
    if (lane == leader) base = atomicAdd(&g_count, (uint32_t)__popc(mask));
    base = __shfl_sync(mask, base, leader);
    uint32_t slot = base + __popc(mask & ((1u << lane) - 1u));
    if (slot < QCAP) {
      uint32_t flags = (okA ? 0u : (1u << 30)) | (okB ? 0u : (1u << 31));
      g_qhdr[slot] = e | flags;
      const FA& ff = okA ? fb : fa;   // failed gamma (A preferred if both)
      QE q;
      q.kc0 = ff.kc.a; q.kc1 = ff.kc.b;
      q.xk0 = ff.xk.a; q.xk1 = ff.xk.b;
      q.x = ff.x; q.v = ff.v; q.U = ff.U;
      q.d = okA ? db : da;
      q.c = okA ? cb : ca;
      q.zc = zc;
      q.d2 = db; q.c2 = cb;          // used only for double-fail (B replay)
      g_qstate[slot] = q;
    }
  }
}

// ---------------------------------------------------------------------------
// Phase 2: resume rejection loops directly from staged state.
// ---------------------------------------------------------------------------
__global__ void __launch_bounds__(256)
phase2_kernel(float* __restrict__ out,
              uint32_t kb0, uint32_t kb1) {
  uint32_t count = min(g_count, QCAP);
  unsigned stride = gridDim.x * 256u;
  for (uint32_t i = blockIdx.x * 256u + threadIdx.x; i < count; i += stride) {
    uint32_t hdr = g_qhdr[i];
    unsigned e = hdr & 0x01FFFFFFu;
    bool fA = (hdr >> 30) & 1u;
    bool fB = (hdr >> 31) & 1u;
    QE q = g_qstate[i];

    float lv = mt_finish(q.kc0, q.kc1, q.xk0, q.xk1,
                         q.x, q.v, q.U, q.d, q.c);

    float z;
    if (fA && fB) {
      FA fb = first_attempt(kb0, kb1, e, q.c2);
      float lvb = mt_finish(fb.kc.a, fb.kc.b, fb.xk.a, fb.xk.b,
                            fb.x, fb.v, fb.U, q.d2, q.c2);
      z = q.zc + (lvb - lv);
    } else {
      float staged = out[e];
      z = fA ? (q.zc + staged - lv) : (q.zc + lv - staged);
    }
    out[e] = __fdividef(1.0f, 1.0f + __expf(z));
  }
}

// ---------------------------------------------------------------------------
extern "C" void kernel_launch(void* const* d_in, const int* in_sizes, int n_in,
                              void* d_out, int out_size) {
  const float* mcp = (const float*)d_in[1];
  for (int i = 0; i < n_in; i++)
    if (in_sizes[i] == 6144) { mcp = (const float*)d_in[i]; break; }

  // root key = threefry_seed(1234) = (0, 1234); key_a, key_b = split(root)
  U2 ka = tf2x32(0u, 1234u, 0u, 0u);
  U2 kb = tf2x32(0u, 1234u, 0u, 1u);

  weights_kernel<<<1, 512>>>();
  dim3 grid(H_ * 2, B_ * C_);   // (half-row, image)
  phase1_kernel<<<grid, 256>>>(mcp, (float*)d_out, ka.a, ka.b, kb.a, kb.b);
  phase2_kernel<<<4096, 256>>>((float*)d_out, kb.a, kb.b);
}

// round 16
// speedup vs baseline: 1.0048x; 1.0017x over previous
#include <cuda_runtime.h>
#include <stdint.h>

// ============================================================================
// ControlPointBetaNoise — exact re-implementation of the JAX reference.
// FINAL (R15 = R14 record holder, 1191.0us, resubmitted unchanged).
// Session wins embodied here:
//   - bit-exact partitionable-threefry / Marsaglia-Tsang reproduction (R2)
//   - lazy advancement of rejection-only keys: 14 TF/elem fast path (R4)
//   - two-phase retry compaction: divergence-free hot kernel (R8)
//   - full sampler-state staging: phase 2 resumes mid-loop, no replay (R10)
//   - block-per-row bicubic with block-uniform y-mix; occupancy-tuned
//     256-thread phase 1 (R12/R14)
// Established limits: phase 1 is at its issue-slot floor (not pipe-bound
// [R11], not occupancy-bound [R14]); 14 TF/elem is the bit-exactness minimum.
// ============================================================================

static const unsigned B_ = 32, C_ = 3, H_ = 512, W_ = 512;
static const unsigned PIX_PER_IMG = H_ * W_;              // 262144 = 1<<18

struct U2 { uint32_t a, b; };

__host__ __device__ __forceinline__ uint32_t rotl32(uint32_t x, int r) {
#ifdef __CUDA_ARCH__
  return __funnelshift_l(x, x, r);
#else
  return (x << r) | (x >> (32 - r));
#endif
}

// threefry2x32, 20 rounds — matches jax._src.prng.threefry2x32 exactly.
__host__ __device__ __forceinline__ U2 tf2x32(uint32_t k0, uint32_t k1,
                                              uint32_t x0, uint32_t x1) {
  uint32_t ks2 = k0 ^ k1 ^ 0x1BD11BDAu;
  x0 += k0; x1 += k1;
#define TF_RND(r) { x0 += x1; x1 = rotl32(x1, (r)); x1 ^= x0; }
  TF_RND(13) TF_RND(15) TF_RND(26) TF_RND(6)
  x0 += k1;  x1 += ks2 + 1u;
  TF_RND(17) TF_RND(29) TF_RND(16) TF_RND(24)
  x0 += ks2; x1 += k0 + 2u;
  TF_RND(13) TF_RND(15) TF_RND(26) TF_RND(6)
  x0 += k0;  x1 += k1 + 3u;
  TF_RND(17) TF_RND(29) TF_RND(16) TF_RND(24)
  x0 += k1;  x1 += ks2 + 4u;
  TF_RND(13) TF_RND(15) TF_RND(26) TF_RND(6)
  x0 += ks2; x1 += k0 + 5u;
#undef TF_RND
  return U2{x0, x1};
}

__device__ __forceinline__ uint32_t bits_scalar(uint32_t k0, uint32_t k1) {
  U2 r = tf2x32(k0, k1, 0u, 0u);
  return r.a ^ r.b;
}

// uniform [0,1): bitcast((bits>>9)|0x3f800000) - 1.0  (matches jax._uniform)
__device__ __forceinline__ float u01_from_bits(uint32_t bits) {
  return __uint_as_float((bits >> 9) | 0x3F800000u) - 1.0f;
}

// XLA f32 erf_inv (Giles polynomial) — what lax.erf_inv lowers to.
__device__ __forceinline__ float erfinv_f32(float x) {
  float w = -log1pf(-x * x);
  float p;
  if (w < 5.0f) {
    w -= 2.5f;
    p = 2.81022636e-08f;
    p = fmaf(p, w, 3.43273939e-07f);
    p = fmaf(p, w, -3.5233877e-06f);
    p = fmaf(p, w, -4.39150654e-06f);
    p = fmaf(p, w, 0.00021858087f);
    p = fmaf(p, w, -0.00125372503f);
    p = fmaf(p, w, -0.00417768164f);
    p = fmaf(p, w, 0.246640727f);
    p = fmaf(p, w, 1.50140941f);
  } else {
    w = sqrtf(w) - 3.0f;
    p = -0.000200214257f;
    p = fmaf(p, w, 0.000100950558f);
    p = fmaf(p, w, 0.00134934322f);
    p = fmaf(p, w, -0.00367342844f);
    p = fmaf(p, w, 0.00573950773f);
    p = fmaf(p, w, -0.0076224613f);
    p = fmaf(p, w, 0.00943887047f);
    p = fmaf(p, w, 1.00167406f);
    p = fmaf(p, w, 2.83297682f);
  }
  return p * x;
}

__device__ __forceinline__ float normal_from_key(uint32_t k0, uint32_t k1) {
  uint32_t bits = bits_scalar(k0, k1);
  float f = u01_from_bits(bits);
  const float LO = __uint_as_float(0xBF7FFFFFu);  // nextafter(-1,0)
  float u = fmaxf(LO, f * 2.0f + LO);
  return 1.41421356237f * erfinv_f32(u);
}

// ---------------------------------------------------------------------------
// Bicubic weight table (jax.image.resize "bicubic", Keys a=-0.5, renormalized)
// + queue reset folded in.
// ---------------------------------------------------------------------------
__device__ float g_w[512][8];

struct __align__(16) QE {
  uint32_t kc0, kc1, xk0, xk1;   // failed gamma: outer + inner keys
  float x, v, U, d;              // failed gamma: current attempt + d
  float c, zc, d2, c2;           // c; zc=log(db/da); d2,c2 for double-fail (B)
};

static const unsigned QCAP = 1u << 23;
__device__ uint32_t g_qhdr[QCAP];
__device__ QE g_qstate[QCAP];
__device__ uint32_t g_count;

__global__ void weights_kernel() {
  int j = threadIdx.x;  // 0..511
  if (j == 0) g_count = 0u;
  float s = (j + 0.5f) * (1.0f / 64.0f) - 0.5f;
  float w[8]; float sum = 0.0f;
#pragma unroll
  for (int i = 0; i < 8; i++) {
    float x = fabsf(s - (float)i);
    float out = ((1.5f * x - 2.5f) * x) * x + 1.0f;
    if (x >= 1.0f) out = ((-0.5f * x + 2.5f) * x - 4.0f) * x + 2.0f;
    if (x >= 2.0f) out = 0.0f;
    w[i] = out; sum += out;
  }
#pragma unroll
  for (int i = 0; i < 8; i++) g_w[j][i] = w[i] / sum;
}

// ---------------------------------------------------------------------------
// Marsaglia–Tsang continuation loop (resumes from a computed attempt).
// ---------------------------------------------------------------------------
__device__ __forceinline__ float mt_finish(uint32_t kl0, uint32_t kl1,
                                           uint32_t xk0, uint32_t xk1,
                                           float x, float v, float U,
                                           float d, float c) {
  for (;;) {
    while (v <= 0.0f) {
      U2 nxt = tf2x32(xk0, xk1, 0u, 0u);
      xk0 = nxt.a; xk1 = nxt.b;
      U2 sub = tf2x32(xk0, xk1, 0u, 1u);
      x = normal_from_key(sub.a, sub.b);
      v = fmaf(c, x, 1.0f);
    }
    float X = x * x;
    float V = (v * v) * v;
    float lV = logf(V);
    bool rej = (U >= 1.0f - 0.0331f * (X * X)) &&
               (logf(U) >= 0.5f * X + d * (1.0f - V + lV));
    if (!rej) return lV;
    U2 nk = tf2x32(kl0, kl1, 0u, 0u);
    kl0 = nk.a; kl1 = nk.b;
    U2 xk = tf2x32(kl0, kl1, 0u, 1u);
    xk0 = xk.a; xk1 = xk.b;
    U2 Uk = tf2x32(kl0, kl1, 0u, 2u);
    U2 sub = tf2x32(xk0, xk1, 0u, 1u);
    x = normal_from_key(sub.a, sub.b);
    v = fmaf(c, x, 1.0f);
    U = u01_from_bits(bits_scalar(Uk.a, Uk.b));
  }
}

struct FA { U2 kc, xk; float x, v, U; };

__device__ __forceinline__ FA first_attempt(uint32_t K0, uint32_t K1,
                                            uint32_t e, float c) {
  FA f;
  U2 ek = tf2x32(K0, K1, 0u, e);
  f.kc = tf2x32(ek.a, ek.b, 0u, 0u);
  f.xk = tf2x32(f.kc.a, f.kc.b, 0u, 1u);
  U2 Uk = tf2x32(f.kc.a, f.kc.b, 0u, 2u);
  U2 sb = tf2x32(f.xk.a, f.xk.b, 0u, 1u);
  f.x = normal_from_key(sb.a, sb.b);
  f.v = fmaf(c, f.x, 1.0f);
  f.U = u01_from_bits(bits_scalar(Uk.a, Uk.b));
  return f;
}

__device__ __forceinline__ bool try_accept(const FA& f, float d, float& lV) {
  float X = f.x * f.x;
  float V = (f.v * f.v) * f.v;
  float l = logf(V);
  bool rej = (f.U >= 1.0f - 0.0331f * (X * X)) &&
             (logf(f.U) >= 0.5f * X + d * (1.0f - V + l));
  lV = l;
  return (f.v > 0.0f) && !rej;
}

// ---------------------------------------------------------------------------
// Phase 1: one block per (image, half-row); one pixel per thread.
// ---------------------------------------------------------------------------
__global__ void __launch_bounds__(256, 6)
phase1_kernel(const float* __restrict__ mcp, float* __restrict__ out,
              uint32_t ka0, uint32_t ka1, uint32_t kb0, uint32_t kb1) {
  __shared__ float Gs[64];
  __shared__ float trow[8];
  unsigned bc = blockIdx.y;
  unsigned y  = blockIdx.x >> 1;
  unsigned xbase = (blockIdx.x & 1u) * 256u;
  unsigned tid = threadIdx.x;
  unsigned x = xbase + tid;

  if (tid < 64) Gs[tid] = fmaf(__ldg(mcp + bc * 64u + tid), 0.9f, 0.05f);
  __syncthreads();
  if (tid < 8) {
    const float* wy = g_w[y];
    float tj = 0.0f;
#pragma unroll
    for (int i = 0; i < 8; i++) tj = fmaf(wy[i], Gs[i * 8 + tid], tj);
    trow[tid] = tj;
  }
  __syncthreads();

  float m = 0.0f;
  {
    const float* wx = g_w[x];
#pragma unroll
    for (int j = 0; j < 8; j++) m = fmaf(wx[j], trow[j], m);
  }

  m = fminf(fmaxf(m, 0.05f), 0.95f);
  float t  = m * (1.0f - m);
  float sd = t - 1e-6f;
  float V_ = t / (sd * sd) - 1.0f;
  float Alpha = fmaxf(m * V_, 0.0f) + 1e-6f;          // >= 1.0027
  float Beta  = fmaxf((1.0f - m) * V_, 0.0f) + 1e-6f; // >= 1.0027
  float da = Alpha - (1.0f / 3.0f);
  float ca = (1.0f / 3.0f) * rsqrtf(da);
  float db = Beta - (1.0f / 3.0f);
  float cb = (1.0f / 3.0f) * rsqrtf(db);

  unsigned e = bc * PIX_PER_IMG + y * 512u + x;

  FA fa = first_attempt(ka0, ka1, e, ca);
  FA fb = first_attempt(kb0, kb1, e, cb);

  float lVa, lVb;
  bool okA = try_accept(fa, da, lVa);
  bool okB = try_accept(fb, db, lVb);
  bool ok = okA && okB;

  float zc = logf(__fdividef(db, da));

  if (ok) {
    float z = zc + (lVb - lVa);
    out[e] = __fdividef(1.0f, 1.0f + __expf(z));
  } else if (okA != okB) {
    out[e] = okA ? lVa : lVb;   // stage accepted gamma's logV
  }

  // warp-aggregated enqueue of failed-state entries
  unsigned mask = __ballot_sync(0xFFFFFFFFu, !ok);
  if (!ok) {
    unsigned leader = __ffs(mask) - 1u;
    unsigned lane = tid & 31u;
    uint32_t base = 0;
    if (lane == leader) base = atomicAdd(&g_count, (uint32_t)__popc(mask));
    base = __shfl_sync(mask, base, leader);
    uint32_t slot = base + __popc(mask & ((1u << lane) - 1u));
    if (slot < QCAP) {
      uint32_t flags = (okA ? 0u : (1u << 30)) | (okB ? 0u : (1u << 31));
      g_qhdr[slot] = e | flags;
      const FA& ff = okA ? fb : fa;   // failed gamma (A preferred if both)
      QE q;
      q.kc0 = ff.kc.a; q.kc1 = ff.kc.b;
      q.xk0 = ff.xk.a; q.xk1 = ff.xk.b;
      q.x = ff.x; q.v = ff.v; q.U = ff.U;
      q.d = okA ? db : da;
      q.c = okA ? cb : ca;
      q.zc = zc;
      q.d2 = db; q.c2 = cb;          // used only for double-fail (B replay)
      g_qstate[slot] = q;
    }
  }
}

// ---------------------------------------------------------------------------
// Phase 2: resume rejection loops directly from staged state.
// ---------------------------------------------------------------------------
__global__ void __launch_bounds__(256)
phase2_kernel(float* __restrict__ out,
              uint32_t kb0, uint32_t kb1) {
  uint32_t count = min(g_count, QCAP);
  unsigned stride = gridDim.x * 256u;
  for (uint32_t i = blockIdx.x * 256u + threadIdx.x; i < count; i += stride) {
    uint32_t hdr = g_qhdr[i];
    unsigned e = hdr & 0x01FFFFFFu;
    bool fA = (hdr >> 30) & 1u;
    bool fB = (hdr >> 31) & 1u;
    QE q = g_qstate[i];

    float lv = mt_finish(q.kc0, q.kc1, q.xk0, q.xk1,
                         q.x, q.v, q.U, q.d, q.c);

    float z;
    if (fA && fB) {
      FA fb = first_attempt(kb0, kb1, e, q.c2);
      float lvb = mt_finish(fb.kc.a, fb.kc.b, fb.xk.a, fb.xk.b,
                            fb.x, fb.v, fb.U, q.d2, q.c2);
      z = q.zc + (lvb - lv);
    } else {
      float staged = out[e];
      z = fA ? (q.zc + staged - lv) : (q.zc + lv - staged);
    }
    out[e] = __fdividef(1.0f, 1.0f + __expf(z));
  }
}

// ---------------------------------------------------------------------------
extern "C" void kernel_launch(void* const* d_in, const int* in_sizes, int n_in,
                              void* d_out, int out_size) {
  const float* mcp = (const float*)d_in[1];
  for (int i = 0; i < n_in; i++)
    if (in_sizes[i] == 6144) { mcp = (const float*)d_in[i]; break; }

  // root key = threefry_seed(1234) = (0, 1234); key_a, key_b = split(root)
  U2 ka = tf2x32(0u, 1234u, 0u, 0u);
  U2 kb = tf2x32(0u, 1234u, 0u, 1u);

  weights_kernel<<<1, 512>>>();
  dim3 grid(H_ * 2, B_ * C_);   // (half-row, image)
  phase1_kernel<<<grid, 256>>>(mcp, (float*)d_out, ka.a, ka.b, kb.a, kb.b);
  phase2_kernel<<<4096, 256>>>((float*)d_out, kb.a, kb.b);
}